// round 5
// baseline (speedup 1.0000x reference)
#include <cuda_runtime.h>
#include <cuda_fp16.h>
#include <cstdint>

// GPTQ int4 dequant GEMM: out[M,N] = x[M,K] @ W[K,N].
// Inputs (harness upcasts fp16 arrays to fp32):
//   x f32[M,K], qweight i32[K/8,N], scales f32[G,N], qzeros i32[G,N/8],
//   g_idx i32[K] (== k/128, folded), out f32[M,N] (rounded through fp16).
//
// Stage 1: cvt_x_kernel: x -> fp16 g_xh (plain order).
// Stage 2: 256x128x32 CTA tile, 256 thr (8 warps = 4m x 2n), warp tile 64x64,
//          mma.sync.m16n8k16, double-buffered dynamic smem, A via cp.async,
//          B dequant (magic-number int4->fp16) -> smem. 1 CTA/SM, tensor-bound.

#define Mdim 4096
#define Kdim 4096
#define Ndim 11008
#define BM 256
#define BN 128
#define BK 32
#define ALD 40    // A smem row stride (halfs)
#define BLD 136   // B smem row stride (halfs)
#define KTILES (Kdim / BK)              // 128
#define ASTAGE (BM * ALD)               // halfs per A buffer
#define BSTAGE (BK * BLD)               // halfs per B buffer
#define DYN_SMEM ((2 * ASTAGE + 2 * BSTAGE) * 2 + 256)

__device__ __half g_xh[(size_t)Mdim * Kdim];   // 32 MB fp16 copy of x

__global__ __launch_bounds__(256)
void cvt_x_kernel(const float* __restrict__ x)
{
    size_t i = ((size_t)blockIdx.x * blockDim.x + threadIdx.x) * 8;
    float4 a = *(const float4*)(x + i);
    float4 b = *(const float4*)(x + i + 4);
    __half2 h[4];
    h[0] = __floats2half2_rn(a.x, a.y);
    h[1] = __floats2half2_rn(a.z, a.w);
    h[2] = __floats2half2_rn(b.x, b.y);
    h[3] = __floats2half2_rn(b.z, b.w);
    *(uint4*)(g_xh + i) = *(uint4*)h;
}

__device__ __forceinline__ unsigned sptr(const void* p) {
    return (unsigned)__cvta_generic_to_shared(p);
}
__device__ __forceinline__ void cpa16(unsigned d, const void* s) {
    asm volatile("cp.async.cg.shared.global [%0], [%1], 16;\n" :: "r"(d), "l"(s));
}
__device__ __forceinline__ void cp_commit() { asm volatile("cp.async.commit_group;\n"); }
__device__ __forceinline__ void cp_wait0()  { asm volatile("cp.async.wait_group 0;\n"); }

__device__ __forceinline__ void ldmA(uint32_t r[4], unsigned a) {
    asm volatile("ldmatrix.sync.aligned.m8n8.x4.shared.b16 {%0,%1,%2,%3}, [%4];\n"
        : "=r"(r[0]), "=r"(r[1]), "=r"(r[2]), "=r"(r[3]) : "r"(a));
}
__device__ __forceinline__ void ldmBt(uint32_t r[4], unsigned a) {
    asm volatile("ldmatrix.sync.aligned.m8n8.x4.trans.shared.b16 {%0,%1,%2,%3}, [%4];\n"
        : "=r"(r[0]), "=r"(r[1]), "=r"(r[2]), "=r"(r[3]) : "r"(a));
}
__device__ __forceinline__ void mma16816(float c[4], const uint32_t a[4], const uint32_t b[2]) {
    asm volatile(
        "mma.sync.aligned.m16n8k16.row.col.f32.f16.f16.f32 "
        "{%0,%1,%2,%3}, {%4,%5,%6,%7}, {%8,%9}, {%0,%1,%2,%3};\n"
        : "+f"(c[0]), "+f"(c[1]), "+f"(c[2]), "+f"(c[3])
        : "r"(a[0]), "r"(a[1]), "r"(a[2]), "r"(a[3]), "r"(b[0]), "r"(b[1]));
}
__device__ __forceinline__ float r16(float v) {
    return __half2float(__float2half_rn(v));
}

__global__ __launch_bounds__(256, 1)
void gptq_gemm_kernel(const int*   __restrict__ qw,
                      const float* __restrict__ sc,
                      const int*   __restrict__ qz,
                      float*       __restrict__ out)
{
    extern __shared__ __half smem[];
    __half* As[2] = { smem, smem + ASTAGE };
    __half* Bs[2] = { smem + 2 * ASTAGE, smem + 2 * ASTAGE + BSTAGE };

    const int tid  = threadIdx.x;
    const int wid  = tid >> 5;
    const int lane = tid & 31;
    const int n0 = blockIdx.x * BN;
    const int m0 = blockIdx.y * BM;

    // ---- A cp.async mapping: one row per thread, 32 halfs = 4x16B ----
    const int arow = tid;
    const __half* gAh = g_xh + (size_t)(m0 + arow) * Kdim;
    const unsigned sA[2] = {
        sptr(&As[0][arow * ALD]),
        sptr(&As[1][arow * ALD])
    };

    // ---- B dequant mapping: 2 cols (nl, nl+1) x 8 k per thread ----
    const int kk8 = tid >> 6;                  // 0..3
    const int nl  = (tid << 1) & 127;          // even local col
    const int gcol = n0 + nl;
    const int* gQbase = qw + (size_t)kk8 * Ndim + gcol;
    const int zsh0 = (nl & 7) * 4;

    // ---- warp tiling: 4m x 2n, warp tile 64x64 ----
    const int wm = wid >> 1;                   // 0..3 -> 64 rows each
    const int wn = wid & 1;                    // 0..1 -> 64 cols each

    unsigned aBase[2], bBase[2];
    {
        const int l15 = lane & 15;
        const int hi8 = (lane >> 4) << 3;
        #pragma unroll
        for (int bu = 0; bu < 2; bu++) {
            aBase[bu] = sptr(&As[bu][(wm * 64 + l15) * ALD + hi8]);
            bBase[bu] = sptr(&Bs[bu][l15 * BLD + wn * 64 + hi8]);
        }
    }

    float acc[4][8][4];
    #pragma unroll
    for (int mt = 0; mt < 4; mt++)
        #pragma unroll
        for (int nt = 0; nt < 8; nt++)
            #pragma unroll
            for (int i = 0; i < 4; i++) acc[mt][nt][i] = 0.f;

    // staging for next B tile
    uint32_t q0s, q1s;
    __half2 s2h, bias2;

    auto ldgB = [&](int it) {
        const int2 qq = *(const int2*)(gQbase + (size_t)(it * 4) * Ndim);
        q0s = (uint32_t)qq.x; q1s = (uint32_t)qq.y;
        const int g = it >> 2;
        float2 sf = *(const float2*)(sc + (size_t)g * Ndim + gcol);
        int qzw = qz[(size_t)g * (Ndim / 8) + (gcol >> 3)];
        int z0 = ((qzw >> zsh0) & 15) + 1;
        int z1 = ((qzw >> (zsh0 + 4)) & 15) + 1;
        s2h   = __floats2half2_rn(sf.x, sf.y);
        bias2 = __floats2half2_rn(1024.f + (float)z0, 1024.f + (float)z1);
    };
    auto stsB = [&](int bu) {
        #pragma unroll
        for (int j = 0; j < 8; j++) {
            uint32_t nib = ((q0s >> (4 * j)) & 15u)
                         | (((q1s >> (4 * j)) & 15u) << 16)
                         | 0x64006400u;                 // half2(1024+w0, 1024+w1)
            __half2 hv = *(__half2*)&nib;
            *(__half2*)&Bs[bu][(kk8 * 8 + j) * BLD + nl] =
                __hmul2(__hsub2(hv, bias2), s2h);       // s*(w-z) in fp16
        }
    };
    auto cpaA = [&](int it, int bu) {
        const __half* src = gAh + it * BK;
        #pragma unroll
        for (int u = 0; u < 4; u++)
            cpa16(sA[bu] + u * 16, src + u * 8);
        cp_commit();
    };

    // ---------------- prologue ----------------
    cpaA(0, 0);
    ldgB(0);
    stsB(0);
    cp_wait0();
    __syncthreads();

    // ---------------- mainloop ----------------
    for (int it = 0; it < KTILES; ++it) {
        const int cur = it & 1;
        const int nx  = cur ^ 1;
        const bool has_next = (it + 1 < KTILES);

        if (has_next) {
            cpaA(it + 1, nx);
            ldgB(it + 1);          // LDGs overlap with MMAs below
        }

        #pragma unroll
        for (int ks = 0; ks < 2; ks++) {
            const unsigned aOff = aBase[cur] + ks * 32;            // k16 * 2B
            const unsigned bOff = bBase[cur] + ks * 16 * BLD * 2;

            uint32_t a[4][4];
            #pragma unroll
            for (int mt = 0; mt < 4; mt++)
                ldmA(a[mt], aOff + mt * 16 * ALD * 2);

            uint32_t b[8][2];
            #pragma unroll
            for (int p = 0; p < 4; p++) {
                uint32_t r[4];
                ldmBt(r, bOff + p * 32);                           // 16 cols * 2B
                b[2 * p][0] = r[0]; b[2 * p][1] = r[1];
                b[2 * p + 1][0] = r[2]; b[2 * p + 1][1] = r[3];
            }

            #pragma unroll
            for (int mt = 0; mt < 4; mt++)
                #pragma unroll
                for (int nt = 0; nt < 8; nt++)
                    mma16816(acc[mt][nt], a[mt], b[nt]);
        }

        if (has_next) stsB(nx);
        cp_wait0();
        __syncthreads();
    }

    // ---------------- epilogue ----------------
    const int r = lane >> 2;
    const int c = (lane & 3) << 1;
    #pragma unroll
    for (int mt = 0; mt < 4; mt++) {
        #pragma unroll
        for (int nt = 0; nt < 8; nt++) {
            const size_t row = (size_t)(m0 + wm * 64 + mt * 16 + r);
            const size_t col = (size_t)(n0 + wn * 64 + nt * 8 + c);
            float* p0 = out + row * Ndim + col;
            *(float2*)p0 = make_float2(r16(acc[mt][nt][0]), r16(acc[mt][nt][1]));
            *(float2*)(p0 + 8 * (size_t)Ndim) =
                make_float2(r16(acc[mt][nt][2]), r16(acc[mt][nt][3]));
        }
    }
}

extern "C" void kernel_launch(void* const* d_in, const int* in_sizes, int n_in,
                              void* d_out, int out_size)
{
    const float* x  = (const float*)d_in[0];
    const int*   qw = (const int*)d_in[1];
    const float* sc = (const float*)d_in[2];
    const int*   qz = (const int*)d_in[3];
    float* out = (float*)d_out;

    cvt_x_kernel<<<(Mdim * (size_t)Kdim) / (256 * 8), 256>>>(x);

    cudaFuncSetAttribute(gptq_gemm_kernel,
                         cudaFuncAttributeMaxDynamicSharedMemorySize, DYN_SMEM);
    dim3 grid(Ndim / BN, Mdim / BM);   // (86, 16)
    gptq_gemm_kernel<<<grid, 256, DYN_SMEM>>>(qw, sc, qz, out);
}

// round 7
// speedup vs baseline: 1.8065x; 1.8065x over previous
#include <cuda_runtime.h>
#include <cuda_fp16.h>
#include <cstdint>

// GPTQ int4 dequant GEMM: out[M,N] = x[M,K] @ W[K,N].
// Inputs (harness upcasts fp16 arrays to fp32):
//   x f32[M,K], qweight i32[K/8,N], scales f32[G,N], qzeros i32[G,N/8],
//   g_idx i32[K] (== k/128, folded), out f32[M,N] (rounded through fp16).
//
// Stage 1: cvt_x_kernel: x -> fp16 g_xh.
// Stage 2: 128x128x32 CTA tile, 256 thr (8 warps = 4m x 2n), warp tile 32x64,
//          mma.sync.m16n8k16. 3-stage smem pipeline: cp.async A two iters
//          ahead (wait_group 1), B dequant regs fetched one iter before STS.
//          2 CTAs/SM.

#define Mdim 4096
#define Kdim 4096
#define Ndim 11008
#define BM 128
#define BN 128
#define BK 32
#define ALD 40
#define BLD 136
#define KTILES (Kdim / BK)              // 128
#define NST 3
#define ASTG (BM * ALD)                 // halfs per A stage (5120)
#define BSTG (BK * BLD)                 // halfs per B stage (4352)
#define DYN_SMEM (NST * (ASTG + BSTG) * 2)

__device__ __half g_xh[(size_t)Mdim * Kdim];

__global__ __launch_bounds__(256)
void cvt_x_kernel(const float* __restrict__ x)
{
    size_t i = ((size_t)blockIdx.x * blockDim.x + threadIdx.x) * 8;
    float4 a = *(const float4*)(x + i);
    float4 b = *(const float4*)(x + i + 4);
    __half2 h[4];
    h[0] = __floats2half2_rn(a.x, a.y);
    h[1] = __floats2half2_rn(a.z, a.w);
    h[2] = __floats2half2_rn(b.x, b.y);
    h[3] = __floats2half2_rn(b.z, b.w);
    *(uint4*)(g_xh + i) = *(uint4*)h;
}

__device__ __forceinline__ unsigned sptr(const void* p) {
    return (unsigned)__cvta_generic_to_shared(p);
}
__device__ __forceinline__ void cpa16(unsigned d, const void* s) {
    asm volatile("cp.async.cg.shared.global [%0], [%1], 16;\n" :: "r"(d), "l"(s));
}
__device__ __forceinline__ void cp_commit() { asm volatile("cp.async.commit_group;\n"); }
__device__ __forceinline__ void cp_wait1()  { asm volatile("cp.async.wait_group 1;\n"); }

__device__ __forceinline__ void ldmA(uint32_t r[4], unsigned a) {
    asm volatile("ldmatrix.sync.aligned.m8n8.x4.shared.b16 {%0,%1,%2,%3}, [%4];\n"
        : "=r"(r[0]), "=r"(r[1]), "=r"(r[2]), "=r"(r[3]) : "r"(a));
}
__device__ __forceinline__ void ldmBt(uint32_t r[4], unsigned a) {
    asm volatile("ldmatrix.sync.aligned.m8n8.x4.trans.shared.b16 {%0,%1,%2,%3}, [%4];\n"
        : "=r"(r[0]), "=r"(r[1]), "=r"(r[2]), "=r"(r[3]) : "r"(a));
}
__device__ __forceinline__ void mma16816(float c[4], const uint32_t a[4], const uint32_t b[2]) {
    asm volatile(
        "mma.sync.aligned.m16n8k16.row.col.f32.f16.f16.f32 "
        "{%0,%1,%2,%3}, {%4,%5,%6,%7}, {%8,%9}, {%0,%1,%2,%3};\n"
        : "+f"(c[0]), "+f"(c[1]), "+f"(c[2]), "+f"(c[3])
        : "r"(a[0]), "r"(a[1]), "r"(a[2]), "r"(a[3]), "r"(b[0]), "r"(b[1]));
}
__device__ __forceinline__ float r16(float v) {
    return __half2float(__float2half_rn(v));
}

struct BStg { uint32_t q0, q1; __half2 s2, b2; };

__global__ __launch_bounds__(256, 2)
void gptq_gemm_kernel(const int*   __restrict__ qw,
                      const float* __restrict__ sc,
                      const int*   __restrict__ qz,
                      float*       __restrict__ out)
{
    extern __shared__ __half smem[];
    __half* Asm = smem;                       // NST stages of ASTG
    __half* Bsm = smem + NST * ASTG;          // NST stages of BSTG

    const int tid  = threadIdx.x;
    const int wid  = tid >> 5;
    const int lane = tid & 31;
    const int n0 = blockIdx.x * BN;
    const int m0 = blockIdx.y * BM;

    // ---- A cp.async mapping: one row, 16 halfs (2x16B) per thread ----
    const int arow  = tid >> 1;
    const int acolh = (tid & 1) << 4;
    const __half* gAh = g_xh + (size_t)(m0 + arow) * Kdim + acolh;
    const unsigned sAo = sptr(Asm) + (arow * ALD + acolh) * 2;   // + stage*ASTG*2

    // ---- B dequant mapping: 2 cols (nl, nl+1) x 8 k per thread ----
    const int kk8 = tid >> 6;
    const int nl  = (tid << 1) & 127;
    const int gcol = n0 + nl;
    const int* gQbase = qw + (size_t)kk8 * Ndim + gcol;
    const int zsh0 = (nl & 7) * 4;
    __half* sBo = Bsm + (kk8 * 8) * BLD + nl;                    // + stage*BSTG

    // ---- warp tiling: 4m x 2n, warp tile 32x64 ----
    const int wm = wid >> 1;
    const int wn = wid & 1;

    unsigned aBase, bBase;
    {
        const int l15 = lane & 15;
        const int hi8 = (lane >> 4) << 3;
        aBase = sptr(Asm) + ((wm * 32 + l15) * ALD + hi8) * 2;
        bBase = sptr(Bsm) + (l15 * BLD + wn * 64 + hi8) * 2;
    }

    float acc[2][8][4];
    #pragma unroll
    for (int mt = 0; mt < 2; mt++)
        #pragma unroll
        for (int nt = 0; nt < 8; nt++)
            #pragma unroll
            for (int i = 0; i < 4; i++) acc[mt][nt][i] = 0.f;

    auto ldgB = [&](int it, BStg& st) {
        const int2 qq = *(const int2*)(gQbase + (size_t)(it * 4) * Ndim);
        st.q0 = (uint32_t)qq.x; st.q1 = (uint32_t)qq.y;
        const int g = it >> 2;
        float2 sf = *(const float2*)(sc + (size_t)g * Ndim + gcol);
        int qzw = qz[(size_t)g * (Ndim / 8) + (gcol >> 3)];
        int z0 = ((qzw >> zsh0) & 15) + 1;
        int z1 = ((qzw >> (zsh0 + 4)) & 15) + 1;
        st.s2 = __floats2half2_rn(sf.x, sf.y);
        st.b2 = __floats2half2_rn(1024.f + (float)z0, 1024.f + (float)z1);
    };
    auto stsB = [&](int stg, const BStg& st) {
        __half* dst = sBo + stg * BSTG;
        #pragma unroll
        for (int j = 0; j < 8; j++) {
            uint32_t nib = ((st.q0 >> (4 * j)) & 15u)
                         | (((st.q1 >> (4 * j)) & 15u) << 16)
                         | 0x64006400u;
            __half2 hv = *(__half2*)&nib;
            *(__half2*)(dst + j * BLD) = __hmul2(__hsub2(hv, st.b2), st.s2);
        }
    };
    auto cpaA = [&](int it, int stg) {
        const __half* src = gAh + it * BK;
        const unsigned d = sAo + stg * (ASTG * 2);
        cpa16(d,      src);
        cpa16(d + 16, src + 8);    // FIXED: +16 bytes (was +32)
    };
    auto compute = [&](int stg) {
        const unsigned aS = aBase + stg * (ASTG * 2);
        const unsigned bS = bBase + stg * (BSTG * 2);
        #pragma unroll
        for (int ks = 0; ks < 2; ks++) {
            uint32_t a[2][4];
            #pragma unroll
            for (int mt = 0; mt < 2; mt++)
                ldmA(a[mt], aS + mt * (16 * ALD * 2) + ks * 32);
            uint32_t b[8][2];
            #pragma unroll
            for (int p = 0; p < 4; p++) {
                uint32_t r[4];
                ldmBt(r, bS + ks * (16 * BLD * 2) + p * 32);
                b[2 * p][0] = r[0]; b[2 * p][1] = r[1];
                b[2 * p + 1][0] = r[2]; b[2 * p + 1][1] = r[3];
            }
            #pragma unroll
            for (int mt = 0; mt < 2; mt++)
                #pragma unroll
                for (int nt = 0; nt < 8; nt++)
                    mma16816(acc[mt][nt], a[mt], b[nt]);
        }
    };

    BStg set0, set1;

    // ---------------- prologue ----------------
    ldgB(0, set0);
    stsB(0, set0);          // B tile0 -> stage0
    ldgB(1, set1);          // B tile1 regs (STS during iter0)
    cpaA(0, 0); cp_commit();
    cpaA(1, 1); cp_commit();
    cp_wait1();             // A(0) done, A(1) in flight
    __syncthreads();

    // ---------------- mainloop (2x unrolled: compile-time reg sets) ----------------
    // iter j: compute stage j%3; ldgB(j+2) + cpaA(j+2 -> (j+2)%3);
    //         stsB(j+1 -> (j+1)%3); wait_group 1; barrier.
    int s_cur = 0;
    for (int it = 0; it < KTILES; it += 2) {
        // ---- even j = it: sts set1, load set0 ----
        {
            const int s2a = s_cur + 2 >= NST ? s_cur + 2 - NST : s_cur + 2;
            const int s1a = s_cur + 1 >= NST ? s_cur + 1 - NST : s_cur + 1;
            if (it + 2 < KTILES) { ldgB(it + 2, set0); cpaA(it + 2, s2a); }
            cp_commit();
            compute(s_cur);
            if (it + 1 < KTILES) stsB(s1a, set1);
            cp_wait1();
            __syncthreads();
            s_cur = s1a;
        }
        // ---- odd j = it+1: sts set0, load set1 ----
        {
            const int s2a = s_cur + 2 >= NST ? s_cur + 2 - NST : s_cur + 2;
            const int s1a = s_cur + 1 >= NST ? s_cur + 1 - NST : s_cur + 1;
            if (it + 3 < KTILES) { ldgB(it + 3, set1); cpaA(it + 3, s2a); }
            cp_commit();
            compute(s_cur);
            if (it + 2 < KTILES) stsB(s1a, set0);
            cp_wait1();
            __syncthreads();
            s_cur = s1a;
        }
    }

    // ---------------- epilogue ----------------
    const int r = lane >> 2;
    const int c = (lane & 3) << 1;
    #pragma unroll
    for (int mt = 0; mt < 2; mt++) {
        #pragma unroll
        for (int nt = 0; nt < 8; nt++) {
            const size_t row = (size_t)(m0 + wm * 32 + mt * 16 + r);
            const size_t col = (size_t)(n0 + wn * 64 + nt * 8 + c);
            float* p0 = out + row * Ndim + col;
            *(float2*)p0 = make_float2(r16(acc[mt][nt][0]), r16(acc[mt][nt][1]));
            *(float2*)(p0 + 8 * (size_t)Ndim) =
                make_float2(r16(acc[mt][nt][2]), r16(acc[mt][nt][3]));
        }
    }
}

extern "C" void kernel_launch(void* const* d_in, const int* in_sizes, int n_in,
                              void* d_out, int out_size)
{
    const float* x  = (const float*)d_in[0];
    const int*   qw = (const int*)d_in[1];
    const float* sc = (const float*)d_in[2];
    const int*   qz = (const int*)d_in[3];
    float* out = (float*)d_out;

    cvt_x_kernel<<<(Mdim * (size_t)Kdim) / (256 * 8), 256>>>(x);

    cudaFuncSetAttribute(gptq_gemm_kernel,
                         cudaFuncAttributeMaxDynamicSharedMemorySize, DYN_SMEM);
    dim3 grid(Ndim / BN, Mdim / BM);   // (86, 32)
    gptq_gemm_kernel<<<grid, 256, DYN_SMEM>>>(qw, sc, qz, out);
}